// round 11
// baseline (speedup 1.0000x reference)
#include <cuda_runtime.h>
#include <cuda_bf16.h>

#define BATCH    4
#define NBOX     8192
#define TILE     128
#define STHREADS 512
#define T_TILES  (NBOX / TILE)                  // 64
#define NPAIRS   (T_TILES * (T_TILES + 1) / 2)  // 2080

// Scratch (no device allocs).
__device__ float g_part2[T_TILES][BATCH * NBOX];   // 8 MB
__device__ float g_stage[8][BATCH * NBOX];         // 1 MB (stage-A output)
__device__ float g_adj[BATCH * NBOX];              // 128 KB
__device__ float g_pmax[32];
__device__ float g_p5[32][5];

// ---------------------------------------------------------------------------
// Kernel 1: symmetric tile-pair kernel. Pair (ti <= tj), 128x128 entries.
// 512 threads = 32 row-groups (4 rows) x 16 col-groups (8 cols); each thread
// owns a 4x8 sub-block (~60 regs -> 2 CTAs/SM, 8 warps/SMSP).
// w(i,j) computed once; credited to row i (w*s_j) and col j (w*s_i).
// Column order rotated ((c+cg)&7) -> conflict-free LDS.
// Areas pre-scaled by 1/C so uni lands in ex2 units via one FMA.
// ---------------------------------------------------------------------------
#define CINV (-0.34657359027997264f)   // 1/C = -ln2/2 ; C = -2/ln2

template<bool DIAG>
__device__ __forceinline__ void tile_body(
    const float4* __restrict__ sboxI, const float2* __restrict__ sasI,
    const float4* __restrict__ sboxJ, const float2* __restrict__ sasJ,
    int rg, int cg, float* __restrict__ racc, float* __restrict__ cacc)
{
    float4 rb[4]; float raInv[4]; float rs[4];
    #pragma unroll
    for (int r = 0; r < 4; ++r) {
        int ir = rg * 4 + r;
        rb[r] = sboxI[ir];
        float2 t = sasI[ir];
        raInv[r] = t.x * CINV;    // area_i / C
        rs[r]    = t.y;
    }

    #pragma unroll
    for (int c = 0; c < 8; ++c) {
        const int jc = cg * 8 + ((c + cg) & 7);   // rotated -> conflict-free
        const float4 jb = sboxJ[jc];
        const float2 ja = sasJ[jc];
        const float jaInv = ja.x * CINV;          // area_j / C
        float ca = 0.0f;
        #pragma unroll
        for (int r = 0; r < 4; ++r) {
            float iw = fmaxf(fminf(rb[r].z, jb.z) - fmaxf(rb[r].x, jb.x), 0.0f);
            float ih = fmaxf(fminf(rb[r].w, jb.w) - fmaxf(rb[r].y, jb.y), 0.0f);
            float inter = iw * ih;
            // uniS = union / C  (negative) ; t = inter / uniS = C * iou
            float uniS = fmaf(inter, -CINV, raInv[r] + jaInv);
            float rc; asm("rcp.approx.ftz.f32 %0, %1;" : "=f"(rc) : "f"(uniS));
            float t = inter * rc;
            float w; asm("ex2.approx.ftz.f32 %0, %1;" : "=f"(w) : "f"(t));
            if (DIAG) w = (jc > rg * 4 + r) ? w : 0.0f;   // strict upper only
            racc[r] = fmaf(w, ja.y, racc[r]);
            ca      = fmaf(w, rs[r], ca);
        }
        cacc[c] = __fadd_rn(cacc[c], ca);   // cacc[c] <-> column jc (constant idx)
    }
}

__global__ __launch_bounds__(STHREADS, 2)
void symm_kernel(const float* __restrict__ boxes,
                 const float* __restrict__ scores)
{
    const int b = blockIdx.y;

    // triangular decode: pair index -> (ti, tj), ti <= tj
    const int p = blockIdx.x;
    int ti = (int)((2.0f * T_TILES + 1.0f
                    - sqrtf((2.0f * T_TILES + 1.0f) * (2.0f * T_TILES + 1.0f) - 8.0f * p)) * 0.5f);
    ti = ti < 0 ? 0 : (ti >= T_TILES ? T_TILES - 1 : ti);
    #pragma unroll 1
    while (ti > 0 && (ti * (2 * T_TILES - ti + 1)) / 2 > p) --ti;
    #pragma unroll 1
    while (((ti + 1) * (2 * T_TILES - ti)) / 2 <= p) ++ti;
    const int tj = ti + (p - (ti * (2 * T_TILES - ti + 1)) / 2);
    const bool diag = (ti == tj);

    __shared__ float4 sboxI[TILE];
    __shared__ float2 sasI[TILE];
    __shared__ float4 sboxJ[TILE];
    __shared__ float2 sasJ[TILE];
    __shared__ float  red[TILE * 33];   // reduce buffer (16.5 KB, reused)

    const float4* __restrict__ box4 = reinterpret_cast<const float4*>(boxes) + (size_t)b * NBOX;
    const float*  __restrict__ sc   = scores + (size_t)b * NBOX;

    const int tid   = threadIdx.x;
    const int rg    = tid >> 4;      // 0..31 (4 rows each)
    const int cg    = tid & 15;      // 0..15 (8 cols each)
    const int ibase = ti * TILE;
    const int jbase = tj * TILE;

    // stage both tiles
    if (tid < TILE) {
        float4 v = box4[ibase + tid];
        sboxI[tid] = v;
        sasI[tid]  = make_float2((v.z - v.x) * (v.w - v.y), sc[ibase + tid]);
    } else if (tid < 2 * TILE) {
        int k = tid - TILE;
        float4 v = box4[jbase + k];
        sboxJ[k] = v;
        sasJ[k]  = make_float2((v.z - v.x) * (v.w - v.y), sc[jbase + k]);
    }
    __syncthreads();

    float racc[4] = {0,0,0,0};
    float cacc[8] = {0,0,0,0,0,0,0,0};

    if (diag) tile_body<true >(sboxI, sasI, sboxJ, sasJ, rg, cg, racc, cacc);
    else      tile_body<false>(sboxI, sasI, sboxJ, sasJ, rg, cg, racc, cacc);

    // ---- row reduce: 128 rows x 16 col-groups (fixed order) ----
    #pragma unroll
    for (int r = 0; r < 4; ++r)
        red[(rg * 4 + r) * 17 + cg] = racc[r];
    __syncthreads();

    float rowsum = 0.0f;
    if (tid < TILE) {
        rowsum = red[tid * 17 + 0];
        #pragma unroll
        for (int k = 1; k < 16; ++k)
            rowsum = __fadd_rn(rowsum, red[tid * 17 + k]);
    }
    __syncthreads();

    // ---- col reduce: 128 cols x 32 row-groups (store at rotated col jc) ----
    #pragma unroll
    for (int c = 0; c < 8; ++c) {
        const int jc = cg * 8 + ((c + cg) & 7);
        red[jc * 33 + rg] = cacc[c];
    }
    __syncthreads();

    float colsum = 0.0f;
    if (tid < TILE) {
        colsum = red[tid * 33 + 0];
        #pragma unroll
        for (int k = 1; k < 32; ++k)
            colsum = __fadd_rn(colsum, red[tid * 33 + k]);
    }

    // ---- store partials: unique (slot, index) writer per CTA ----
    if (tid < TILE) {
        if (diag) {
            const float E2 = 0.13533528323661270f;   // exp(-2) self term
            float v = __fadd_rn(__fadd_rn(rowsum, colsum), E2 * sasI[tid].y);
            g_part2[ti][(size_t)b * NBOX + ibase + tid] = v;
        } else {
            g_part2[tj][(size_t)b * NBOX + ibase + tid] = rowsum;   // rows of tile ti
            g_part2[ti][(size_t)b * NBOX + jbase + tid] = colsum;   // cols of tile tj
        }
    }
}

// ---------------------------------------------------------------------------
// Kernel 2a: stage A reduce — 64 slots -> 8 groups. 256 CTAs x 256 threads.
// CTA: group g = blockIdx.x & 7, chunk = blockIdx.x >> 3 (32 chunks of 256 f4).
// ---------------------------------------------------------------------------
__global__ __launch_bounds__(256)
void reduceA_kernel()
{
    const int g     = blockIdx.x & 7;
    const int chunk = blockIdx.x >> 3;
    const int idx   = chunk * 256 + threadIdx.x;   // f4 index, [0, 8192)

    float4 a = reinterpret_cast<const float4*>(g_part2[g * 8 + 0])[idx];
    #pragma unroll
    for (int s = 1; s < 8; ++s) {
        float4 v = reinterpret_cast<const float4*>(g_part2[g * 8 + s])[idx];
        a.x = __fadd_rn(a.x, v.x); a.y = __fadd_rn(a.y, v.y);
        a.z = __fadd_rn(a.z, v.z); a.w = __fadd_rn(a.w, v.w);
    }
    reinterpret_cast<float4*>(g_stage[g])[idx] = a;
}

// ---------------------------------------------------------------------------
// Kernel 2b: stage B reduce — 8 groups -> g_adj, + per-CTA max.
// 32 CTAs x 256 threads, 1 f4 per thread.
// ---------------------------------------------------------------------------
__global__ __launch_bounds__(256)
void reduceB_kernel()
{
    const int idx = blockIdx.x * 256 + threadIdx.x;   // f4 index

    float4 a = reinterpret_cast<const float4*>(g_stage[0])[idx];
    #pragma unroll
    for (int s = 1; s < 8; ++s) {
        float4 v = reinterpret_cast<const float4*>(g_stage[s])[idx];
        a.x = __fadd_rn(a.x, v.x); a.y = __fadd_rn(a.y, v.y);
        a.z = __fadd_rn(a.z, v.z); a.w = __fadd_rn(a.w, v.w);
    }
    reinterpret_cast<float4*>(g_adj)[idx] = a;

    __shared__ float smax[8];
    float m = fmaxf(fmaxf(a.x, a.y), fmaxf(a.z, a.w));
    #pragma unroll
    for (int o = 16; o; o >>= 1) m = fmaxf(m, __shfl_xor_sync(0xffffffffu, m, o));
    if ((threadIdx.x & 31) == 0) smax[threadIdx.x >> 5] = m;
    __syncthreads();
    if (threadIdx.x == 0) {
        float mm = smax[0];
        #pragma unroll
        for (int w = 1; w < 8; ++w) mm = fmaxf(mm, smax[w]);
        g_pmax[blockIdx.x] = mm;
    }
}

// ---------------------------------------------------------------------------
// Kernel 3: partial softmax sums. 32 CTAs (8 per batch) x 256 threads.
// ---------------------------------------------------------------------------
__global__ __launch_bounds__(256)
void softpart_kernel(const float* __restrict__ boxes)
{
    const int cta = blockIdx.x;
    const int b   = cta >> 3;
    const int t   = threadIdx.x;

    float m = g_pmax[b * 8 + 0];
    #pragma unroll
    for (int k = 1; k < 8; ++k) m = fmaxf(m, g_pmax[b * 8 + k]);

    const int idx = cta * 256 + t;    // f4 index into g_adj
    const float4 ad = reinterpret_cast<const float4*>(g_adj)[idx];
    const float4* __restrict__ box4 = reinterpret_cast<const float4*>(boxes);

    float e0 = __expf(ad.x - m);
    float e1 = __expf(ad.y - m);
    float e2 = __expf(ad.z - m);
    float e3 = __expf(ad.w - m);

    float4 b0 = box4[idx * 4 + 0];
    float4 b1 = box4[idx * 4 + 1];
    float4 b2 = box4[idx * 4 + 2];
    float4 b3 = box4[idx * 4 + 3];

    float se  = ((e0 + e1) + (e2 + e3));
    float sx1 = fmaf(e0, b0.x, fmaf(e1, b1.x, fmaf(e2, b2.x, e3 * b3.x)));
    float sy1 = fmaf(e0, b0.y, fmaf(e1, b1.y, fmaf(e2, b2.y, e3 * b3.y)));
    float sx2 = fmaf(e0, b0.z, fmaf(e1, b1.z, fmaf(e2, b2.z, e3 * b3.z)));
    float sy2 = fmaf(e0, b0.w, fmaf(e1, b1.w, fmaf(e2, b2.w, e3 * b3.w)));

    __shared__ float s5[5][8];
    #pragma unroll
    for (int o = 16; o; o >>= 1) {
        se  += __shfl_xor_sync(0xffffffffu, se,  o);
        sx1 += __shfl_xor_sync(0xffffffffu, sx1, o);
        sy1 += __shfl_xor_sync(0xffffffffu, sy1, o);
        sx2 += __shfl_xor_sync(0xffffffffu, sx2, o);
        sy2 += __shfl_xor_sync(0xffffffffu, sy2, o);
    }
    if ((t & 31) == 0) {
        int w = t >> 5;
        s5[0][w] = se; s5[1][w] = sx1; s5[2][w] = sy1; s5[3][w] = sx2; s5[4][w] = sy2;
    }
    __syncthreads();
    if (t < 5) {
        float a = s5[t][0];
        #pragma unroll
        for (int w = 1; w < 8; ++w) a = __fadd_rn(a, s5[t][w]);
        g_p5[cta][t] = a;
    }
}

// ---------------------------------------------------------------------------
// Kernel 4: final combine. 4 CTAs x 32 threads.
// ---------------------------------------------------------------------------
__global__ __launch_bounds__(32)
void final_kernel(float* __restrict__ out)
{
    const int b = blockIdx.x;
    if (threadIdx.x == 0) {
        float a[5] = {0.f, 0.f, 0.f, 0.f, 0.f};
        #pragma unroll
        for (int k = 0; k < 8; ++k)
            #pragma unroll
            for (int q = 0; q < 5; ++q)
                a[q] = __fadd_rn(a[q], g_p5[b * 8 + k][q]);
        float inv = 1.0f / a[0];
        out[b * 4 + 0] = a[1] * inv;
        out[b * 4 + 1] = a[2] * inv;
        out[b * 4 + 2] = a[3] * inv;
        out[b * 4 + 3] = a[4] * inv;
    }
}

// ---------------------------------------------------------------------------
extern "C" void kernel_launch(void* const* d_in, const int* in_sizes, int n_in,
                              void* d_out, int out_size)
{
    const float* boxes  = (const float*)d_in[0];
    const float* scores = (const float*)d_in[1];
    // Defensive: metadata order should be (boxes, scores); swap if sizes say otherwise.
    if (n_in >= 2 && in_sizes[0] == BATCH * NBOX && in_sizes[1] == BATCH * NBOX * 4) {
        const float* tmp = boxes; boxes = scores; scores = tmp;
    }
    float* out = (float*)d_out;

    symm_kernel<<<dim3(NPAIRS, BATCH), STHREADS>>>(boxes, scores);
    reduceA_kernel<<<256, 256>>>();
    reduceB_kernel<<<32, 256>>>();
    softpart_kernel<<<32, 256>>>(boxes);
    final_kernel<<<BATCH, 32>>>(out);
}

// round 13
// speedup vs baseline: 2.0174x; 2.0174x over previous
#include <cuda_runtime.h>
#include <cuda_bf16.h>

#define BATCH    4
#define NBOX     8192
#define TILE     128
#define THREADS  256
#define T_TILES  (NBOX / TILE)                  // 64
#define NPAIRS   (T_TILES * (T_TILES + 1) / 2)  // 2080

#define CINV (-0.34657359027997264f)   // 1/C = -ln2/2 ; C = -2/ln2

// Scratch (no device allocs).
__device__ float g_part2[T_TILES][BATCH * NBOX];   // 8 MB
__device__ float g_stage[8][BATCH * NBOX];         // 1 MB
__device__ float g_adj[BATCH * NBOX];              // 128 KB
__device__ float g_pmax[32];
__device__ float g_p5[32][5];

// ---------------------------------------------------------------------------
// Kernel 1: symmetric tile-pair kernel (R10 config: 8x8 sub-block, 256 thr).
// Pair (ti <= tj), 128x128 entries. w(i,j) computed once; credited to
// row i (w*s_j) and col j (w*s_i). Column order rotated ((c+cg)&7) so the
// j-tile LDS is bank-conflict-free (rotation only in addresses, never as a
// runtime register-array index). Areas pre-scaled by 1/C: per entry
// FADD + FFMA + RCP + FMUL + EX2.
// ---------------------------------------------------------------------------
template<bool DIAG>
__device__ __forceinline__ void tile_body(
    const float4* __restrict__ sboxI, const float2* __restrict__ sasI,
    const float4* __restrict__ sboxJ, const float2* __restrict__ sasJ,
    int rg, int cg, float* __restrict__ racc, float* __restrict__ cacc)
{
    float4 rb[8]; float raInv[8]; float rs[8];
    #pragma unroll
    for (int r = 0; r < 8; ++r) {
        int ir = rg * 8 + r;
        rb[r] = sboxI[ir];
        float2 t = sasI[ir];
        raInv[r] = t.x * CINV;    // area_i / C
        rs[r]    = t.y;
    }

    #pragma unroll
    for (int c = 0; c < 8; ++c) {
        const int jc = cg * 8 + ((c + cg) & 7);   // rotated -> conflict-free LDS
        const float4 jb = sboxJ[jc];
        const float2 ja = sasJ[jc];
        const float jaInv = ja.x * CINV;          // area_j / C
        float ca = 0.0f;
        #pragma unroll
        for (int r = 0; r < 8; ++r) {
            float iw = fmaxf(fminf(rb[r].z, jb.z) - fmaxf(rb[r].x, jb.x), 0.0f);
            float ih = fmaxf(fminf(rb[r].w, jb.w) - fmaxf(rb[r].y, jb.y), 0.0f);
            float inter = iw * ih;
            // uniS = union / C (negative); t = inter / uniS = C * iou
            float uniS = fmaf(inter, -CINV, raInv[r] + jaInv);
            float rc; asm("rcp.approx.ftz.f32 %0, %1;" : "=f"(rc) : "f"(uniS));
            float t = inter * rc;
            float w; asm("ex2.approx.ftz.f32 %0, %1;" : "=f"(w) : "f"(t));
            if (DIAG) w = (jc > rg * 8 + r) ? w : 0.0f;   // strict upper only
            racc[r] = fmaf(w, ja.y, racc[r]);
            ca      = fmaf(w, rs[r], ca);
        }
        cacc[c] = __fadd_rn(cacc[c], ca);   // cacc[c] <-> column jc (constant idx)
    }
}

__global__ __launch_bounds__(THREADS, 2)
void symm_kernel(const float* __restrict__ boxes,
                 const float* __restrict__ scores)
{
    const int b = blockIdx.y;

    // triangular decode: pair index -> (ti, tj), ti <= tj
    const int p = blockIdx.x;
    int ti = (int)((2.0f * T_TILES + 1.0f
                    - sqrtf((2.0f * T_TILES + 1.0f) * (2.0f * T_TILES + 1.0f) - 8.0f * p)) * 0.5f);
    ti = ti < 0 ? 0 : (ti >= T_TILES ? T_TILES - 1 : ti);
    #pragma unroll 1
    while (ti > 0 && (ti * (2 * T_TILES - ti + 1)) / 2 > p) --ti;
    #pragma unroll 1
    while (((ti + 1) * (2 * T_TILES - ti)) / 2 <= p) ++ti;
    const int tj = ti + (p - (ti * (2 * T_TILES - ti + 1)) / 2);
    const bool diag = (ti == tj);

    __shared__ float4 sboxI[TILE];
    __shared__ float2 sasI[TILE];
    __shared__ float4 sboxJ[TILE];
    __shared__ float2 sasJ[TILE];
    __shared__ float  red[TILE * 17];   // 16-way reduce buffer (padded)

    const float4* __restrict__ box4 = reinterpret_cast<const float4*>(boxes) + (size_t)b * NBOX;
    const float*  __restrict__ sc   = scores + (size_t)b * NBOX;

    const int tid   = threadIdx.x;
    const int rg    = tid >> 4;      // 0..15
    const int cg    = tid & 15;      // 0..15
    const int ibase = ti * TILE;
    const int jbase = tj * TILE;

    // stage both tiles
    if (tid < TILE) {
        float4 v = box4[ibase + tid];
        sboxI[tid] = v;
        sasI[tid]  = make_float2((v.z - v.x) * (v.w - v.y), sc[ibase + tid]);
    } else {
        int k = tid - TILE;
        float4 v = box4[jbase + k];
        sboxJ[k] = v;
        sasJ[k]  = make_float2((v.z - v.x) * (v.w - v.y), sc[jbase + k]);
    }
    __syncthreads();

    float racc[8] = {0,0,0,0,0,0,0,0};
    float cacc[8] = {0,0,0,0,0,0,0,0};

    if (diag) tile_body<true >(sboxI, sasI, sboxJ, sasJ, rg, cg, racc, cacc);
    else      tile_body<false>(sboxI, sasI, sboxJ, sasJ, rg, cg, racc, cacc);

    // ---- row reduce: sum over 16 col-groups (fixed order -> deterministic) ----
    #pragma unroll
    for (int r = 0; r < 8; ++r)
        red[(rg * 8 + r) * 17 + cg] = racc[r];
    __syncthreads();

    float rowsum = 0.0f;
    if (tid < TILE) {
        rowsum = red[tid * 17 + 0];
        #pragma unroll
        for (int k = 1; k < 16; ++k)
            rowsum = __fadd_rn(rowsum, red[tid * 17 + k]);
    }
    __syncthreads();

    // ---- col reduce: sum over 16 row-groups (store at rotated col jc) ----
    #pragma unroll
    for (int c = 0; c < 8; ++c) {
        const int jc = cg * 8 + ((c + cg) & 7);
        red[jc * 17 + rg] = cacc[c];
    }
    __syncthreads();

    float colsum = 0.0f;
    if (tid < TILE) {
        colsum = red[tid * 17 + 0];
        #pragma unroll
        for (int k = 1; k < 16; ++k)
            colsum = __fadd_rn(colsum, red[tid * 17 + k]);
    }

    // ---- store partials: unique (slot, index) writer per CTA ----
    if (tid < TILE) {
        if (diag) {
            const float E2 = 0.13533528323661270f;   // exp(-2) self term
            float v = __fadd_rn(__fadd_rn(rowsum, colsum), E2 * sasI[tid].y);
            g_part2[ti][(size_t)b * NBOX + ibase + tid] = v;
        } else {
            g_part2[tj][(size_t)b * NBOX + ibase + tid] = rowsum;   // rows of tile ti
            g_part2[ti][(size_t)b * NBOX + jbase + tid] = colsum;   // cols of tile tj
        }
    }
}

// ---------------------------------------------------------------------------
// Kernel 2a: stage A reduce — 64 slots -> 8 groups. 256 CTAs x 256 threads.
// ---------------------------------------------------------------------------
__global__ __launch_bounds__(256)
void reduceA_kernel()
{
    const int g     = blockIdx.x & 7;
    const int chunk = blockIdx.x >> 3;
    const int idx   = chunk * 256 + threadIdx.x;   // f4 index, [0, 8192)

    float4 a = reinterpret_cast<const float4*>(g_part2[g * 8 + 0])[idx];
    #pragma unroll
    for (int s = 1; s < 8; ++s) {
        float4 v = reinterpret_cast<const float4*>(g_part2[g * 8 + s])[idx];
        a.x = __fadd_rn(a.x, v.x); a.y = __fadd_rn(a.y, v.y);
        a.z = __fadd_rn(a.z, v.z); a.w = __fadd_rn(a.w, v.w);
    }
    reinterpret_cast<float4*>(g_stage[g])[idx] = a;
}

// ---------------------------------------------------------------------------
// Kernel 2b: stage B reduce — 8 groups -> g_adj, + per-CTA max.
// 32 CTAs x 256 threads.
// ---------------------------------------------------------------------------
__global__ __launch_bounds__(256)
void reduceB_kernel()
{
    const int idx = blockIdx.x * 256 + threadIdx.x;   // f4 index

    float4 a = reinterpret_cast<const float4*>(g_stage[0])[idx];
    #pragma unroll
    for (int s = 1; s < 8; ++s) {
        float4 v = reinterpret_cast<const float4*>(g_stage[s])[idx];
        a.x = __fadd_rn(a.x, v.x); a.y = __fadd_rn(a.y, v.y);
        a.z = __fadd_rn(a.z, v.z); a.w = __fadd_rn(a.w, v.w);
    }
    reinterpret_cast<float4*>(g_adj)[idx] = a;

    __shared__ float smax[8];
    float m = fmaxf(fmaxf(a.x, a.y), fmaxf(a.z, a.w));
    #pragma unroll
    for (int o = 16; o; o >>= 1) m = fmaxf(m, __shfl_xor_sync(0xffffffffu, m, o));
    if ((threadIdx.x & 31) == 0) smax[threadIdx.x >> 5] = m;
    __syncthreads();
    if (threadIdx.x == 0) {
        float mm = smax[0];
        #pragma unroll
        for (int w = 1; w < 8; ++w) mm = fmaxf(mm, smax[w]);
        g_pmax[blockIdx.x] = mm;
    }
}

// ---------------------------------------------------------------------------
// Kernel 3: partial softmax sums. 32 CTAs (8 per batch) x 256 threads.
// ---------------------------------------------------------------------------
__global__ __launch_bounds__(256)
void softpart_kernel(const float* __restrict__ boxes)
{
    const int cta = blockIdx.x;
    const int b   = cta >> 3;
    const int t   = threadIdx.x;

    float m = g_pmax[b * 8 + 0];
    #pragma unroll
    for (int k = 1; k < 8; ++k) m = fmaxf(m, g_pmax[b * 8 + k]);

    const int idx = cta * 256 + t;    // f4 index into g_adj
    const float4 ad = reinterpret_cast<const float4*>(g_adj)[idx];
    const float4* __restrict__ box4 = reinterpret_cast<const float4*>(boxes);

    float e0 = __expf(ad.x - m);
    float e1 = __expf(ad.y - m);
    float e2 = __expf(ad.z - m);
    float e3 = __expf(ad.w - m);

    float4 b0 = box4[idx * 4 + 0];
    float4 b1 = box4[idx * 4 + 1];
    float4 b2 = box4[idx * 4 + 2];
    float4 b3 = box4[idx * 4 + 3];

    float se  = ((e0 + e1) + (e2 + e3));
    float sx1 = fmaf(e0, b0.x, fmaf(e1, b1.x, fmaf(e2, b2.x, e3 * b3.x)));
    float sy1 = fmaf(e0, b0.y, fmaf(e1, b1.y, fmaf(e2, b2.y, e3 * b3.y)));
    float sx2 = fmaf(e0, b0.z, fmaf(e1, b1.z, fmaf(e2, b2.z, e3 * b3.z)));
    float sy2 = fmaf(e0, b0.w, fmaf(e1, b1.w, fmaf(e2, b2.w, e3 * b3.w)));

    __shared__ float s5[5][8];
    #pragma unroll
    for (int o = 16; o; o >>= 1) {
        se  += __shfl_xor_sync(0xffffffffu, se,  o);
        sx1 += __shfl_xor_sync(0xffffffffu, sx1, o);
        sy1 += __shfl_xor_sync(0xffffffffu, sy1, o);
        sx2 += __shfl_xor_sync(0xffffffffu, sx2, o);
        sy2 += __shfl_xor_sync(0xffffffffu, sy2, o);
    }
    if ((t & 31) == 0) {
        int w = t >> 5;
        s5[0][w] = se; s5[1][w] = sx1; s5[2][w] = sy1; s5[3][w] = sx2; s5[4][w] = sy2;
    }
    __syncthreads();
    if (t < 5) {
        float a = s5[t][0];
        #pragma unroll
        for (int w = 1; w < 8; ++w) a = __fadd_rn(a, s5[t][w]);
        g_p5[cta][t] = a;
    }
}

// ---------------------------------------------------------------------------
// Kernel 4: final combine. 4 CTAs x 32 threads.
// ---------------------------------------------------------------------------
__global__ __launch_bounds__(32)
void final_kernel(float* __restrict__ out)
{
    const int b = blockIdx.x;
    if (threadIdx.x == 0) {
        float a[5] = {0.f, 0.f, 0.f, 0.f, 0.f};
        #pragma unroll
        for (int k = 0; k < 8; ++k)
            #pragma unroll
            for (int q = 0; q < 5; ++q)
                a[q] = __fadd_rn(a[q], g_p5[b * 8 + k][q]);
        float inv = 1.0f / a[0];
        out[b * 4 + 0] = a[1] * inv;
        out[b * 4 + 1] = a[2] * inv;
        out[b * 4 + 2] = a[3] * inv;
        out[b * 4 + 3] = a[4] * inv;
    }
}

// ---------------------------------------------------------------------------
extern "C" void kernel_launch(void* const* d_in, const int* in_sizes, int n_in,
                              void* d_out, int out_size)
{
    const float* boxes  = (const float*)d_in[0];
    const float* scores = (const float*)d_in[1];
    // Defensive: metadata order should be (boxes, scores); swap if sizes say otherwise.
    if (n_in >= 2 && in_sizes[0] == BATCH * NBOX && in_sizes[1] == BATCH * NBOX * 4) {
        const float* tmp = boxes; boxes = scores; scores = tmp;
    }
    float* out = (float*)d_out;

    symm_kernel<<<dim3(NPAIRS, BATCH), THREADS>>>(boxes, scores);
    reduceA_kernel<<<256, 256>>>();
    reduceB_kernel<<<32, 256>>>();
    softpart_kernel<<<32, 256>>>(boxes);
    final_kernel<<<BATCH, 32>>>(out);
}